// round 13
// baseline (speedup 1.0000x reference)
#include <cuda_runtime.h>
#include <cuda_fp16.h>
#include <stdint.h>

#define DIM 1280
#define NC  8192
#define MAX_ROWS 16384

#define BM 128
#define BN 256
#define BK 64                      // fp16 k-elements per chunk (128 B rows)
#define NCH (DIM / BK)             // 20
#define TILES_N (NC / BN)          // 32
#define NSTAGE 3

// rigorous margin: approx err (2-sided) <= 2*2^-11*||a||*||b|| ~ 8.8e-4,
// + fp16 dist storage rounding (2-sided) ~ 6e-4  => 1.5e-3 < EPS
#define EPS 2e-3f

// stage layout: A 128x64 fp16 = 16 KB, B 256x64 fp16 = 32 KB
#define ST_A 0
#define ST_B 16384
#define STAGE_BYTES 49152
#define SMEM_DYN (NSTAGE * STAGE_BYTES)   // 147456

#define MAXCAND 256

// ---- device scratch ----
__device__ float    g_xf[(size_t)MAX_ROWS * DIM];   // normalized x fp32
__device__ __half   g_a_h[(size_t)MAX_ROWS * DIM];
__device__ float    g_bT[(size_t)NC * DIM];         // codebook^T fp32
__device__ __half   g_b_h[(size_t)NC * DIM];
__device__ float    g_d2[NC];
__device__ __half   g_dist[(size_t)MAX_ROWS * NC];  // approx distances (fp16)
__device__ uint32_t g_tmin[(size_t)MAX_ROWS * TILES_N];  // per-tile row min (fkey)
__device__ int      g_idx[MAX_ROWS];

// ---------------------------------------------------------------------------
__device__ __forceinline__ uint32_t smem_u32(const void* p) {
    uint32_t a;
    asm("{ .reg .u64 t; cvta.to.shared.u64 t, %1; cvt.u32.u64 %0, t; }"
        : "=r"(a) : "l"(p));
    return a;
}
__device__ __forceinline__ unsigned int fkey(float f) {
    unsigned int u = __float_as_uint(f);
    return (u & 0x80000000u) ? ~u : (u | 0x80000000u);
}
__device__ __forceinline__ float unfkey(unsigned int u) {
    return (u & 0x80000000u) ? __uint_as_float(u & 0x7FFFFFFFu)
                             : __uint_as_float(~u);
}
#define SWZ(o) ((o) ^ ((((uint32_t)(o)) >> 3) & 0x70))

__device__ __forceinline__ void cp16(uint32_t dst, const void* src) {
    asm volatile("cp.async.cg.shared.global [%0], [%1], 16;" :: "r"(dst), "l"(src));
}
#define CP_COMMIT() asm volatile("cp.async.commit_group;" ::: "memory")

__device__ __forceinline__ void ldsm4(uint32_t& r0, uint32_t& r1, uint32_t& r2,
                                      uint32_t& r3, uint32_t addr) {
    asm volatile("ldmatrix.sync.aligned.m8n8.x4.shared.b16 {%0,%1,%2,%3}, [%4];"
                 : "=r"(r0), "=r"(r1), "=r"(r2), "=r"(r3) : "r"(addr));
}
__device__ __forceinline__ void mma_f16(float* c, uint32_t a0, uint32_t a1,
                                        uint32_t a2, uint32_t a3,
                                        uint32_t b0, uint32_t b1) {
    asm volatile(
        "mma.sync.aligned.m16n8k16.row.col.f32.f16.f16.f32 "
        "{%0,%1,%2,%3}, {%4,%5,%6,%7}, {%8,%9}, {%0,%1,%2,%3};"
        : "+f"(c[0]), "+f"(c[1]), "+f"(c[2]), "+f"(c[3])
        : "r"(a0), "r"(a1), "r"(a2), "r"(a3), "r"(b0), "r"(b1));
}

// ---------------------------------------------------------------------------
__global__ void normalize_split_kernel(const float* __restrict__ x, int n_rows) {
    int gwarp = (blockIdx.x * blockDim.x + threadIdx.x) >> 5;
    int lane  = threadIdx.x & 31;
    if (gwarp >= n_rows) return;
    const float* xr = x + (size_t)gwarp * DIM;
    float s = 0.f;
    #pragma unroll 4
    for (int k = lane; k < DIM; k += 32) { float v = xr[k]; s = fmaf(v, v, s); }
    #pragma unroll
    for (int o = 16; o; o >>= 1) s += __shfl_xor_sync(0xFFFFFFFFu, s, o);
    float norm = fmaxf(sqrtf(s), 1e-12f);
    float* xo = g_xf + (size_t)gwarp * DIM;
    __half* oh = g_a_h + (size_t)gwarp * DIM;
    #pragma unroll 4
    for (int k = lane; k < DIM; k += 32) {
        float v = xr[k] / norm;
        xo[k] = v;
        oh[k] = __float2half_rn(v);
    }
}

__global__ void transpose_split_kernel(const float* __restrict__ cb) {
    __shared__ float t[32][33];
    int n0 = blockIdx.x * 32;
    int k0 = blockIdx.y * 32;
    int tx = threadIdx.x, ty = threadIdx.y;  // 32 x 8
    #pragma unroll
    for (int j = 0; j < 4; j++)
        t[ty + 8 * j][tx] = cb[(size_t)(k0 + ty + 8 * j) * NC + n0 + tx];
    __syncthreads();
    #pragma unroll
    for (int j = 0; j < 4; j++) {
        int n = n0 + ty + 8 * j;
        int k = k0 + tx;
        float v = t[tx][ty + 8 * j];
        g_bT[(size_t)n * DIM + k] = v;
        g_b_h[(size_t)n * DIM + k] = __float2half_rn(v);
    }
}

__global__ void d2_kernel(const float* __restrict__ cb) {
    int c = blockIdx.x * blockDim.x + threadIdx.x;
    if (c >= NC) return;
    float s = 0.f;
    #pragma unroll 4
    for (int k = 0; k < DIM; k++) { float v = cb[(size_t)k * NC + c]; s = fmaf(v, v, s); }
    g_d2[c] = s;
}

// ---------------------------------------------------------------------------
// single-pass fp16 mma.sync GEMM 128x256, warp tile 64x64, 3-stage pipeline.
// epilogue stores fp16 dist + per-row tile-min (fkey) for pruned selection.
__global__ __launch_bounds__(256, 1)
void gemm_mma_kernel(int mtiles) {
    extern __shared__ char smem[];
    __shared__ float d2s[BN];
    __shared__ uint32_t smin[BM];

    const uint32_t sb = smem_u32(smem);
    const int tid  = threadIdx.x;
    const int wid  = tid >> 5;
    const int lane = tid & 31;

    int bid = blockIdx.x;
    int mt = bid % mtiles;
    int nt = bid / mtiles;
    const int rowBase = mt * BM;
    const int colBase = nt * BN;

    d2s[tid] = g_d2[colBase + tid];        // 256 threads cover BN=256
    if (tid < BM) smin[tid] = 0xFFFFFFFFu;
    __syncthreads();

    const __half* Ah = g_a_h + (size_t)rowBase * DIM;
    const __half* Bh = g_b_h + (size_t)colBase * DIM;

    auto load_chunk = [&](int c, int st) {
        uint32_t base = sb + st * STAGE_BYTES;
        int kb = c * BK;
        #pragma unroll
        for (int j = 0; j < 4; j++) {              // A: 128 rows
            int i = tid + j * 256;
            int row = i >> 3, c16 = i & 7;
            uint32_t off = SWZ(row * 128 + c16 * 16);
            cp16(base + ST_A + off, Ah + (size_t)row * DIM + kb + c16 * 8);
        }
        #pragma unroll
        for (int j = 0; j < 8; j++) {              // B: 256 rows
            int i = tid + j * 256;
            int row = i >> 3, c16 = i & 7;
            uint32_t off = SWZ(row * 128 + c16 * 16);
            cp16(base + ST_B + off, Bh + (size_t)row * DIM + kb + c16 * 8);
        }
        CP_COMMIT();
    };

    // warp tiling: 2 (M) x 4 (N), warp tile 64 x 64
    const int wm = (wid >> 2) * 64;
    const int wn = (wid & 3) * 64;

    float acc[4][8][4];
    #pragma unroll
    for (int i = 0; i < 4; i++)
        #pragma unroll
        for (int j = 0; j < 8; j++)
            #pragma unroll
            for (int k = 0; k < 4; k++) acc[i][j][k] = 0.f;

    const int lm = lane >> 3;
    const int lr = lane & 7;
    const int a_row  = wm + ((lm & 1) << 3) + lr;
    const int a_koff = (lm >> 1) << 4;
    const int b_row  = wn + ((lm >> 1) << 3) + lr;
    const int b_koff = (lm & 1) << 4;

    load_chunk(0, 0);
    load_chunk(1, 1);

    for (int c = 0; c < NCH; c++) {
        if (c + 1 < NCH) {
            asm volatile("cp.async.wait_group 1;" ::: "memory");
        } else {
            asm volatile("cp.async.wait_group 0;" ::: "memory");
        }
        __syncthreads();
        if (c + 2 < NCH) load_chunk(c + 2, (c + 2) % NSTAGE);

        uint32_t base = sb + (c % NSTAGE) * STAGE_BYTES;
        #pragma unroll
        for (int ks = 0; ks < 4; ks++) {
            uint32_t ah[4][4], bh[8][2];
            #pragma unroll
            for (int ma = 0; ma < 4; ma++) {
                uint32_t ra = SWZ((a_row + ma * 16) * 128 + ks * 32 + a_koff);
                ldsm4(ah[ma][0], ah[ma][1], ah[ma][2], ah[ma][3], base + ST_A + ra);
            }
            #pragma unroll
            for (int nb = 0; nb < 4; nb++) {
                uint32_t rb = SWZ((b_row + nb * 16) * 128 + ks * 32 + b_koff);
                ldsm4(bh[2 * nb][0], bh[2 * nb][1], bh[2 * nb + 1][0], bh[2 * nb + 1][1],
                      base + ST_B + rb);
            }
            #pragma unroll
            for (int ma = 0; ma < 4; ma++)
                #pragma unroll
                for (int na = 0; na < 8; na++)
                    mma_f16(acc[ma][na], ah[ma][0], ah[ma][1], ah[ma][2], ah[ma][3],
                            bh[na][0], bh[na][1]);
        }
    }

    // ---- epilogue: store fp16 dist (streaming) + per-row tile-min ----
    // acc[ma][na][c]: row = wm+ma*16+(c>>1)*8+(lane>>2); col = wn+na*8+2*(lane&3)+(c&1)
    const int erow = lane >> 2;
    const int ecol = 2 * (lane & 3);
    #pragma unroll
    for (int ma = 0; ma < 4; ma++) {
        #pragma unroll
        for (int h = 0; h < 2; h++) {
            int row = rowBase + wm + ma * 16 + h * 8 + erow;
            float vmin = 3.402823e38f;
            #pragma unroll
            for (int na = 0; na < 8; na++) {
                int cl = wn + na * 8 + ecol;
                float dx = d2s[cl]     - 2.0f * acc[ma][na][2 * h];
                float dy = d2s[cl + 1] - 2.0f * acc[ma][na][2 * h + 1];
                vmin = fminf(vmin, fminf(dx, dy));
                __half2 hv = __floats2half2_rn(dx, dy);
                __stcs((uint32_t*)(g_dist + (size_t)row * NC + colBase + cl),
                       *(uint32_t*)&hv);
            }
            // reduce over the lane-quad (lanes differing in bits 0-1 share the row)
            uint32_t kv = fkey(vmin);
            uint32_t o1 = __shfl_xor_sync(0xFFFFFFFFu, kv, 1); kv = (o1 < kv) ? o1 : kv;
            uint32_t o2 = __shfl_xor_sync(0xFFFFFFFFu, kv, 2); kv = (o2 < kv) ? o2 : kv;
            if ((lane & 3) == 0)
                atomicMin(&smin[wm + ma * 16 + h * 8 + erow], kv);
        }
    }
    __syncthreads();
    if (tid < BM)
        g_tmin[(size_t)(rowBase + tid) * TILES_N + nt] = smin[tid];
}

// ---------------------------------------------------------------------------
// per-row: tile-min prune -> scan only qualifying tiles -> exact fp32 rescue
__global__ __launch_bounds__(128, 8)
void select_kernel() {
    __shared__ float tmins[TILES_N];
    __shared__ float thr_s;
    __shared__ unsigned long long wmin[4];
    __shared__ unsigned long long sbest;
    __shared__ int cands[MAXCAND];
    __shared__ int ncand;

    const int row  = blockIdx.x;
    const int tid  = threadIdx.x;
    const int wid  = tid >> 5;
    const int lane = tid & 31;

    if (tid < TILES_N) {
        float f = unfkey(g_tmin[(size_t)row * TILES_N + tid]);
        tmins[tid] = f;
        float mm = f;
        #pragma unroll
        for (int o = 16; o; o >>= 1)
            mm = fminf(mm, __shfl_xor_sync(0xFFFFFFFFu, mm, o));
        if (tid == 0) thr_s = mm + EPS;
    }
    if (tid == 0) { ncand = 0; sbest = ~0ull; }
    __syncthreads();

    const float thr = thr_s;
    const uint32_t* dr = (const uint32_t*)(g_dist + (size_t)row * NC);

    unsigned long long key = ~0ull;
    for (int t = 0; t < TILES_N; t++) {
        if (tmins[t] > thr) continue;
        uint32_t q = dr[t * 128 + tid];        // 2 halves per thread, 128 thr = 256 cols
        float2 f = __half22float2(*(__half2*)&q);
        int c0 = t * BN + tid * 2;
        if (f.x <= thr) {
            int p = atomicAdd(&ncand, 1);
            if (p < MAXCAND) cands[p] = c0;
            unsigned long long pk =
                ((unsigned long long)fkey(f.x) << 32) | (unsigned int)c0;
            key = (pk < key) ? pk : key;
        }
        if (f.y <= thr) {
            int p = atomicAdd(&ncand, 1);
            if (p < MAXCAND) cands[p] = c0 + 1;
            unsigned long long pk =
                ((unsigned long long)fkey(f.y) << 32) | (unsigned int)(c0 + 1);
            key = (pk < key) ? pk : key;
        }
    }
    #pragma unroll
    for (int o = 16; o; o >>= 1) {
        unsigned long long other = __shfl_xor_sync(0xFFFFFFFFu, key, o);
        key = (other < key) ? other : key;
    }
    if (lane == 0) wmin[wid] = key;
    __syncthreads();

    int nc = ncand; if (nc > MAXCAND) nc = MAXCAND;
    if (nc <= 1) {
        if (tid == 0) {
            unsigned long long k = wmin[0];
            #pragma unroll
            for (int w = 1; w < 4; w++) k = (wmin[w] < k) ? wmin[w] : k;
            g_idx[row] = (int)(k & 0xFFFFFFFFull);
        }
        return;
    }

    // exact fp32 refine: one warp per candidate, round-robin
    const float* xr = g_xf + (size_t)row * DIM;
    for (int ci = wid; ci < nc; ci += 4) {
        int c = cands[ci];
        const float* bc = g_bT + (size_t)c * DIM;
        float p = 0.f;
        #pragma unroll
        for (int e = 0; e < DIM / 32; e++) {
            int k = lane + 32 * e;
            p = fmaf(xr[k], bc[k], p);
        }
        #pragma unroll
        for (int o = 16; o; o >>= 1) p += __shfl_xor_sync(0xFFFFFFFFu, p, o);
        if (lane == 0) {
            float dist = g_d2[c] - 2.0f * p;
            unsigned long long pk =
                ((unsigned long long)fkey(dist) << 32) | (unsigned int)c;
            atomicMin(&sbest, pk);
        }
    }
    __syncthreads();
    if (tid == 0) g_idx[row] = (int)(sbest & 0xFFFFFFFFull);
}

// ---------------------------------------------------------------------------
__global__ void write_inds_kernel(float* __restrict__ out, int n_rows) {
    int r = blockIdx.x * blockDim.x + threadIdx.x;
    if (r < n_rows) out[r] = (float)g_idx[r];
}

__global__ void gather_kernel(const float* __restrict__ cb,
                              float* __restrict__ out,
                              int n_rows, long long offset) {
    int r = blockIdx.x * blockDim.x + threadIdx.x;
    int d = blockIdx.y;
    if (r >= n_rows) return;
    int ind = g_idx[r];
    out[offset + (size_t)d * n_rows + r] = cb[(size_t)d * NC + ind];
}

// ---------------------------------------------------------------------------
extern "C" void kernel_launch(void* const* d_in, const int* in_sizes, int n_in,
                              void* d_out, int out_size) {
    const float* x  = (const float*)d_in[0];
    const float* cb = (const float*)d_in[1];
    float* out = (float*)d_out;

    int n_rows = in_sizes[0] / DIM;
    if (n_rows > MAX_ROWS) n_rows = MAX_ROWS;

    static int smem_set = 0;
    if (!smem_set) {
        cudaFuncSetAttribute(gemm_mma_kernel,
                             cudaFuncAttributeMaxDynamicSharedMemorySize, SMEM_DYN);
        smem_set = 1;
    }

    // phase 0: prep
    normalize_split_kernel<<<(n_rows * 32 + 255) / 256, 256>>>(x, n_rows);
    dim3 tg(NC / 32, DIM / 32);
    transpose_split_kernel<<<tg, dim3(32, 8)>>>(cb);
    d2_kernel<<<(NC + 255) / 256, 256>>>(cb);

    // phase 1: single-pass fp16 GEMM -> fp16 dist + tile mins
    int mtiles = (n_rows + BM - 1) / BM;
    gemm_mma_kernel<<<mtiles * TILES_N, 256, SMEM_DYN>>>(mtiles);

    // phase 2: pruned per-row selection + exact rescue
    select_kernel<<<n_rows, 128>>>();

    // phase 3: outputs [inds (n_rows)] ++ [quantized (DIM*n_rows)]
    long long full = (long long)n_rows + (long long)n_rows * DIM;
    if ((long long)out_size >= full) {
        write_inds_kernel<<<(n_rows + 255) / 256, 256>>>(out, n_rows);
        dim3 g2((n_rows + 255) / 256, DIM);
        gather_kernel<<<g2, 256>>>(cb, out, n_rows, (long long)n_rows);
    } else if ((long long)out_size == (long long)n_rows * DIM) {
        dim3 g2((n_rows + 255) / 256, DIM);
        gather_kernel<<<g2, 256>>>(cb, out, n_rows, 0);
    } else {
        write_inds_kernel<<<(n_rows + 255) / 256, 256>>>(out, n_rows);
    }
}

// round 14
// speedup vs baseline: 1.5083x; 1.5083x over previous
#include <cuda_runtime.h>
#include <cuda_fp16.h>
#include <stdint.h>

#define DIM 1280
#define NC  8192
#define MAX_ROWS 16384

#define BM 128
#define BN 128
#define BK 64                      // fp16 k-elements per chunk (128 B rows)
#define NCH (DIM / BK)             // 20
#define TILES_N (NC / BN)          // 64
#define NSTAGE 3

// rigorous margin: approx err (2-sided) <= 2*2^-11*||a||*||b|| ~ 8.8e-4,
// + fp16 dist storage rounding (2-sided) ~ 6e-4  => 1.5e-3 < EPS
#define EPS 2e-3f

// stage layout: A 128x64 fp16 = 16 KB, B 128x64 fp16 = 16 KB
#define ST_A 0
#define ST_B 16384
#define STAGE_BYTES 32768
#define SMEM_DYN (NSTAGE * STAGE_BYTES)   // 98304 -> 2 CTAs/SM

#define MAXCAND 256

// ---- device scratch ----
__device__ float  g_xf[(size_t)MAX_ROWS * DIM];   // normalized x fp32
__device__ __half g_a_h[(size_t)MAX_ROWS * DIM];
__device__ float  g_bT[(size_t)NC * DIM];         // codebook^T fp32
__device__ __half g_b_h[(size_t)NC * DIM];
__device__ float  g_d2[NC];
__device__ __half g_dist[(size_t)MAX_ROWS * NC];  // approx distances (fp16)
__device__ int    g_idx[MAX_ROWS];

// ---------------------------------------------------------------------------
__device__ __forceinline__ uint32_t smem_u32(const void* p) {
    uint32_t a;
    asm("{ .reg .u64 t; cvta.to.shared.u64 t, %1; cvt.u32.u64 %0, t; }"
        : "=r"(a) : "l"(p));
    return a;
}
__device__ __forceinline__ unsigned int fkey(float f) {
    unsigned int u = __float_as_uint(f);
    return (u & 0x80000000u) ? ~u : (u | 0x80000000u);
}
#define SWZ(o) ((o) ^ ((((uint32_t)(o)) >> 3) & 0x70))

__device__ __forceinline__ void cp16(uint32_t dst, const void* src) {
    asm volatile("cp.async.cg.shared.global [%0], [%1], 16;" :: "r"(dst), "l"(src));
}
#define CP_COMMIT() asm volatile("cp.async.commit_group;" ::: "memory")

__device__ __forceinline__ void ldsm4(uint32_t& r0, uint32_t& r1, uint32_t& r2,
                                      uint32_t& r3, uint32_t addr) {
    asm volatile("ldmatrix.sync.aligned.m8n8.x4.shared.b16 {%0,%1,%2,%3}, [%4];"
                 : "=r"(r0), "=r"(r1), "=r"(r2), "=r"(r3) : "r"(addr));
}
__device__ __forceinline__ void mma_f16(float* c, uint32_t a0, uint32_t a1,
                                        uint32_t a2, uint32_t a3,
                                        uint32_t b0, uint32_t b1) {
    asm volatile(
        "mma.sync.aligned.m16n8k16.row.col.f32.f16.f16.f32 "
        "{%0,%1,%2,%3}, {%4,%5,%6,%7}, {%8,%9}, {%0,%1,%2,%3};"
        : "+f"(c[0]), "+f"(c[1]), "+f"(c[2]), "+f"(c[3])
        : "r"(a0), "r"(a1), "r"(a2), "r"(a3), "r"(b0), "r"(b1));
}

// ---------------------------------------------------------------------------
__global__ void normalize_split_kernel(const float* __restrict__ x, int n_rows) {
    int gwarp = (blockIdx.x * blockDim.x + threadIdx.x) >> 5;
    int lane  = threadIdx.x & 31;
    if (gwarp >= n_rows) return;
    const float* xr = x + (size_t)gwarp * DIM;
    float s = 0.f;
    #pragma unroll 4
    for (int k = lane; k < DIM; k += 32) { float v = xr[k]; s = fmaf(v, v, s); }
    #pragma unroll
    for (int o = 16; o; o >>= 1) s += __shfl_xor_sync(0xFFFFFFFFu, s, o);
    float norm = fmaxf(sqrtf(s), 1e-12f);
    float* xo = g_xf + (size_t)gwarp * DIM;
    __half* oh = g_a_h + (size_t)gwarp * DIM;
    #pragma unroll 4
    for (int k = lane; k < DIM; k += 32) {
        float v = xr[k] / norm;
        xo[k] = v;
        oh[k] = __float2half_rn(v);
    }
}

__global__ void transpose_split_kernel(const float* __restrict__ cb) {
    __shared__ float t[32][33];
    int n0 = blockIdx.x * 32;
    int k0 = blockIdx.y * 32;
    int tx = threadIdx.x, ty = threadIdx.y;  // 32 x 8
    #pragma unroll
    for (int j = 0; j < 4; j++)
        t[ty + 8 * j][tx] = cb[(size_t)(k0 + ty + 8 * j) * NC + n0 + tx];
    __syncthreads();
    #pragma unroll
    for (int j = 0; j < 4; j++) {
        int n = n0 + ty + 8 * j;
        int k = k0 + tx;
        float v = t[tx][ty + 8 * j];
        g_bT[(size_t)n * DIM + k] = v;
        g_b_h[(size_t)n * DIM + k] = __float2half_rn(v);
    }
}

__global__ void d2_kernel(const float* __restrict__ cb) {
    int c = blockIdx.x * blockDim.x + threadIdx.x;
    if (c >= NC) return;
    float s = 0.f;
    #pragma unroll 4
    for (int k = 0; k < DIM; k++) { float v = cb[(size_t)k * NC + c]; s = fmaf(v, v, s); }
    g_d2[c] = s;
}

// ---------------------------------------------------------------------------
// single-pass fp16 mma.sync GEMM 128x128, warp tile 64x32, 3-stage pipeline,
// 2 CTAs/SM. epilogue stores approx dist = d2 - 2*d3 as fp16 (streaming).
__global__ __launch_bounds__(256, 2)
void gemm_mma_kernel(int mtiles) {
    extern __shared__ char smem[];
    __shared__ float d2s[BN];

    const uint32_t sb = smem_u32(smem);
    const int tid  = threadIdx.x;
    const int wid  = tid >> 5;
    const int lane = tid & 31;

    int bid = blockIdx.x;
    int mt = bid % mtiles;
    int nt = bid / mtiles;
    const int rowBase = mt * BM;
    const int colBase = nt * BN;

    if (tid < BN) d2s[tid] = g_d2[colBase + tid];
    __syncthreads();

    const __half* Ah = g_a_h + (size_t)rowBase * DIM;
    const __half* Bh = g_b_h + (size_t)colBase * DIM;

    auto load_chunk = [&](int c, int st) {
        uint32_t base = sb + st * STAGE_BYTES;
        int kb = c * BK;
        #pragma unroll
        for (int j = 0; j < 4; j++) {              // A: 128 rows x 8 c16
            int i = tid + j * 256;
            int row = i >> 3, c16 = i & 7;
            uint32_t off = SWZ(row * 128 + c16 * 16);
            cp16(base + ST_A + off, Ah + (size_t)row * DIM + kb + c16 * 8);
        }
        #pragma unroll
        for (int j = 0; j < 4; j++) {              // B: 128 rows x 8 c16
            int i = tid + j * 256;
            int row = i >> 3, c16 = i & 7;
            uint32_t off = SWZ(row * 128 + c16 * 16);
            cp16(base + ST_B + off, Bh + (size_t)row * DIM + kb + c16 * 8);
        }
        CP_COMMIT();
    };

    // warp tiling: 2 (M) x 4 (N); warp tile 64 x 32
    const int wm = (wid >> 2) * 64;
    const int wn = (wid & 3) * 32;

    float acc[4][4][4];
    #pragma unroll
    for (int i = 0; i < 4; i++)
        #pragma unroll
        for (int j = 0; j < 4; j++)
            #pragma unroll
            for (int k = 0; k < 4; k++) acc[i][j][k] = 0.f;

    const int lm = lane >> 3;
    const int lr = lane & 7;
    const int a_row  = wm + ((lm & 1) << 3) + lr;
    const int a_koff = (lm >> 1) << 4;
    const int b_row  = wn + ((lm >> 1) << 3) + lr;
    const int b_koff = (lm & 1) << 4;

    load_chunk(0, 0);
    load_chunk(1, 1);

    for (int c = 0; c < NCH; c++) {
        if (c + 1 < NCH) {
            asm volatile("cp.async.wait_group 1;" ::: "memory");
        } else {
            asm volatile("cp.async.wait_group 0;" ::: "memory");
        }
        __syncthreads();
        if (c + 2 < NCH) load_chunk(c + 2, (c + 2) % NSTAGE);

        uint32_t base = sb + (c % NSTAGE) * STAGE_BYTES;
        #pragma unroll
        for (int ks = 0; ks < 4; ks++) {
            uint32_t ah[4][4], bh[4][2];
            #pragma unroll
            for (int ma = 0; ma < 4; ma++) {
                uint32_t ra = SWZ((a_row + ma * 16) * 128 + ks * 32 + a_koff);
                ldsm4(ah[ma][0], ah[ma][1], ah[ma][2], ah[ma][3], base + ST_A + ra);
            }
            #pragma unroll
            for (int nb = 0; nb < 2; nb++) {
                uint32_t rb = SWZ((b_row + nb * 16) * 128 + ks * 32 + b_koff);
                ldsm4(bh[2 * nb][0], bh[2 * nb][1], bh[2 * nb + 1][0], bh[2 * nb + 1][1],
                      base + ST_B + rb);
            }
            #pragma unroll
            for (int ma = 0; ma < 4; ma++)
                #pragma unroll
                for (int na = 0; na < 4; na++)
                    mma_f16(acc[ma][na], ah[ma][0], ah[ma][1], ah[ma][2], ah[ma][3],
                            bh[na][0], bh[na][1]);
        }
    }

    // ---- epilogue: store approx distances as fp16 (streaming) ----
    const int erow = lane >> 2;
    const int ecol = 2 * (lane & 3);
    #pragma unroll
    for (int ma = 0; ma < 4; ma++) {
        #pragma unroll
        for (int h = 0; h < 2; h++) {
            int row = rowBase + wm + ma * 16 + h * 8 + erow;
            #pragma unroll
            for (int na = 0; na < 4; na++) {
                int cl = wn + na * 8 + ecol;
                float dx = d2s[cl]     - 2.0f * acc[ma][na][2 * h];
                float dy = d2s[cl + 1] - 2.0f * acc[ma][na][2 * h + 1];
                __half2 hv = __floats2half2_rn(dx, dy);
                __stcs((uint32_t*)(g_dist + (size_t)row * NC + colBase + cl),
                       *(uint32_t*)&hv);
            }
        }
    }
}

// ---------------------------------------------------------------------------
// per-row: approx min, candidates within EPS, exact fp32 refine (warp/candidate)
// writes g_idx AND (optionally) the float inds output directly.
__global__ __launch_bounds__(256, 4)
void select_kernel(float* __restrict__ out_inds) {
    __shared__ unsigned long long wmin[8];
    __shared__ unsigned long long rowmin_s;
    __shared__ unsigned long long sbest;
    __shared__ int cands[MAXCAND];
    __shared__ int ncand;

    const int row  = blockIdx.x;
    const int tid  = threadIdx.x;
    const int wid  = tid >> 5;
    const int lane = tid & 31;

    const uint4* dr4 = (const uint4*)(g_dist + (size_t)row * NC);

    float v[32];
    unsigned long long key = ~0ull;
    #pragma unroll
    for (int j = 0; j < 4; j++) {
        uint4 q = dr4[tid + 256 * j];
        int cbase = (tid + 256 * j) * 8;
        uint32_t w[4] = {q.x, q.y, q.z, q.w};
        #pragma unroll
        for (int p = 0; p < 4; p++) {
            __half2 h2 = *(__half2*)&w[p];
            float2 f = __half22float2(h2);
            v[j * 8 + 2 * p]     = f.x;
            v[j * 8 + 2 * p + 1] = f.y;
            unsigned long long pk0 =
                ((unsigned long long)fkey(f.x) << 32) | (unsigned int)(cbase + 2 * p);
            unsigned long long pk1 =
                ((unsigned long long)fkey(f.y) << 32) | (unsigned int)(cbase + 2 * p + 1);
            key = (pk0 < key) ? pk0 : key;
            key = (pk1 < key) ? pk1 : key;
        }
    }
    #pragma unroll
    for (int o = 16; o; o >>= 1) {
        unsigned long long other = __shfl_xor_sync(0xFFFFFFFFu, key, o);
        key = (other < key) ? other : key;
    }
    if (lane == 0) wmin[wid] = key;
    if (tid == 0) { ncand = 0; sbest = ~0ull; }
    __syncthreads();
    if (tid == 0) {
        unsigned long long k = wmin[0];
        #pragma unroll
        for (int w = 1; w < 8; w++) k = (wmin[w] < k) ? wmin[w] : k;
        rowmin_s = k;
    }
    __syncthreads();

    unsigned long long rk = rowmin_s;
    unsigned int mku = (unsigned int)(rk >> 32);
    float m = (mku & 0x80000000u) ? __uint_as_float(mku & 0x7FFFFFFFu)
                                  : __uint_as_float(~mku);
    float thr = m + EPS;

    #pragma unroll
    for (int j = 0; j < 32; j++) {
        if (v[j] <= thr) {
            int c = ((tid + 256 * (j >> 3)) * 8) + (j & 7);
            int p = atomicAdd(&ncand, 1);
            if (p < MAXCAND) cands[p] = c;
        }
    }
    __syncthreads();

    int nc = ncand; if (nc > MAXCAND) nc = MAXCAND;
    if (nc <= 1) {
        if (tid == 0) {
            int idx = (int)(rk & 0xFFFFFFFFull);
            g_idx[row] = idx;
            if (out_inds) out_inds[row] = (float)idx;
        }
        return;
    }

    // exact fp32 refine: one warp per candidate, round-robin
    const float* xr = g_xf + (size_t)row * DIM;
    for (int ci = wid; ci < nc; ci += 8) {
        int c = cands[ci];
        const float* bc = g_bT + (size_t)c * DIM;
        float p = 0.f;
        #pragma unroll
        for (int e = 0; e < DIM / 32; e++) {
            int k = lane + 32 * e;
            p = fmaf(xr[k], bc[k], p);
        }
        #pragma unroll
        for (int o = 16; o; o >>= 1) p += __shfl_xor_sync(0xFFFFFFFFu, p, o);
        if (lane == 0) {
            float dist = g_d2[c] - 2.0f * p;
            unsigned long long pk =
                ((unsigned long long)fkey(dist) << 32) | (unsigned int)c;
            atomicMin(&sbest, pk);
        }
    }
    __syncthreads();
    if (tid == 0) {
        int idx = (int)(sbest & 0xFFFFFFFFull);
        g_idx[row] = idx;
        if (out_inds) out_inds[row] = (float)idx;
    }
}

// ---------------------------------------------------------------------------
__global__ void write_inds_kernel(float* __restrict__ out, int n_rows) {
    int r = blockIdx.x * blockDim.x + threadIdx.x;
    if (r < n_rows) out[r] = (float)g_idx[r];
}

__global__ void gather_kernel(const float* __restrict__ cb,
                              float* __restrict__ out,
                              int n_rows, long long offset) {
    int r = blockIdx.x * blockDim.x + threadIdx.x;
    int d = blockIdx.y;
    if (r >= n_rows) return;
    int ind = g_idx[r];
    out[offset + (size_t)d * n_rows + r] = cb[(size_t)d * NC + ind];
}

// ---------------------------------------------------------------------------
extern "C" void kernel_launch(void* const* d_in, const int* in_sizes, int n_in,
                              void* d_out, int out_size) {
    const float* x  = (const float*)d_in[0];
    const float* cb = (const float*)d_in[1];
    float* out = (float*)d_out;

    int n_rows = in_sizes[0] / DIM;
    if (n_rows > MAX_ROWS) n_rows = MAX_ROWS;

    static int smem_set = 0;
    if (!smem_set) {
        cudaFuncSetAttribute(gemm_mma_kernel,
                             cudaFuncAttributeMaxDynamicSharedMemorySize, SMEM_DYN);
        smem_set = 1;
    }

    // phase 0: prep
    normalize_split_kernel<<<(n_rows * 32 + 255) / 256, 256>>>(x, n_rows);
    dim3 tg(NC / 32, DIM / 32);
    transpose_split_kernel<<<tg, dim3(32, 8)>>>(cb);
    d2_kernel<<<(NC + 255) / 256, 256>>>(cb);

    // phase 1: single-pass fp16 GEMM -> approx dist matrix (fp16)
    int mtiles = (n_rows + BM - 1) / BM;
    gemm_mma_kernel<<<mtiles * TILES_N, 256, SMEM_DYN>>>(mtiles);

    // phase 2+3: selection (+ inds output fused) then gather
    long long full = (long long)n_rows + (long long)n_rows * DIM;
    if ((long long)out_size >= full) {
        select_kernel<<<n_rows, 256>>>(out);
        dim3 g2((n_rows + 255) / 256, DIM);
        gather_kernel<<<g2, 256>>>(cb, out, n_rows, (long long)n_rows);
    } else if ((long long)out_size == (long long)n_rows * DIM) {
        select_kernel<<<n_rows, 256>>>(nullptr);
        dim3 g2((n_rows + 255) / 256, DIM);
        gather_kernel<<<g2, 256>>>(cb, out, n_rows, 0);
    } else {
        select_kernel<<<n_rows, 256>>>(out);
    }
}

// round 15
// speedup vs baseline: 1.5840x; 1.0501x over previous
#include <cuda_runtime.h>
#include <cuda_fp16.h>
#include <stdint.h>

#define DIM 1280
#define NC  8192
#define MAX_ROWS 16384

#define BM 128
#define BN 128
#define BK 64                      // fp16 k-elements per chunk (128 B rows)
#define NCH (DIM / BK)             // 20
#define TILES_N (NC / BN)          // 64
#define NSTAGE 3

// rigorous margin: approx err (2-sided) <= 2*2^-11*||a||*||b|| ~ 8.8e-4,
// + fp16 dist storage rounding (2-sided) ~ 6e-4  => 1.5e-3 < EPS
#define EPS 2e-3f

// stage layout: A 128x64 fp16 = 16 KB, B 128x64 fp16 = 16 KB
#define ST_A 0
#define ST_B 16384
#define STAGE_BYTES 32768
#define SMEM_DYN (NSTAGE * STAGE_BYTES)   // 98304 -> 2 CTAs/SM

#define MAXCAND 256

// ---- device scratch ----
__device__ float  g_xf[(size_t)MAX_ROWS * DIM];   // normalized x fp32
__device__ __half g_a_h[(size_t)MAX_ROWS * DIM];
__device__ float  g_bT[(size_t)NC * DIM];         // codebook^T fp32
__device__ __half g_b_h[(size_t)NC * DIM];
__device__ float  g_d2[NC];
__device__ __half g_dist[(size_t)MAX_ROWS * NC];  // approx distances (fp16)
__device__ int    g_idx[MAX_ROWS];

// ---------------------------------------------------------------------------
__device__ __forceinline__ uint32_t smem_u32(const void* p) {
    uint32_t a;
    asm("{ .reg .u64 t; cvta.to.shared.u64 t, %1; cvt.u32.u64 %0, t; }"
        : "=r"(a) : "l"(p));
    return a;
}
__device__ __forceinline__ unsigned int fkey(float f) {
    unsigned int u = __float_as_uint(f);
    return (u & 0x80000000u) ? ~u : (u | 0x80000000u);
}
#define SWZ(o) ((o) ^ ((((uint32_t)(o)) >> 3) & 0x70))

__device__ __forceinline__ void cp16(uint32_t dst, const void* src) {
    asm volatile("cp.async.cg.shared.global [%0], [%1], 16;" :: "r"(dst), "l"(src));
}
#define CP_COMMIT() asm volatile("cp.async.commit_group;" ::: "memory")

__device__ __forceinline__ void ldsm4(uint32_t& r0, uint32_t& r1, uint32_t& r2,
                                      uint32_t& r3, uint32_t addr) {
    asm volatile("ldmatrix.sync.aligned.m8n8.x4.shared.b16 {%0,%1,%2,%3}, [%4];"
                 : "=r"(r0), "=r"(r1), "=r"(r2), "=r"(r3) : "r"(addr));
}
__device__ __forceinline__ void mma_f16(float* c, uint32_t a0, uint32_t a1,
                                        uint32_t a2, uint32_t a3,
                                        uint32_t b0, uint32_t b1) {
    asm volatile(
        "mma.sync.aligned.m16n8k16.row.col.f32.f16.f16.f32 "
        "{%0,%1,%2,%3}, {%4,%5,%6,%7}, {%8,%9}, {%0,%1,%2,%3};"
        : "+f"(c[0]), "+f"(c[1]), "+f"(c[2]), "+f"(c[3])
        : "r"(a0), "r"(a1), "r"(a2), "r"(a3), "r"(b0), "r"(b1));
}

// ---------------------------------------------------------------------------
// fused prep: [0, nbN) normalize rows | [nbN, nbN+nbT) transpose cb | rest d2
__global__ void prep_kernel(const float* __restrict__ x,
                            const float* __restrict__ cb,
                            int n_rows, int nbN, int nbT) {
    __shared__ float t[32][33];
    const int b   = blockIdx.x;
    const int tid = threadIdx.x;

    if (b < nbN) {
        // ---- normalize + fp16 split (warp per row) ----
        int gwarp = (b * 256 + tid) >> 5;
        int lane  = tid & 31;
        if (gwarp >= n_rows) return;
        const float* xr = x + (size_t)gwarp * DIM;
        float s = 0.f;
        #pragma unroll 4
        for (int k = lane; k < DIM; k += 32) { float v = xr[k]; s = fmaf(v, v, s); }
        #pragma unroll
        for (int o = 16; o; o >>= 1) s += __shfl_xor_sync(0xFFFFFFFFu, s, o);
        float norm = fmaxf(sqrtf(s), 1e-12f);
        float* xo = g_xf + (size_t)gwarp * DIM;
        __half* oh = g_a_h + (size_t)gwarp * DIM;
        #pragma unroll 4
        for (int k = lane; k < DIM; k += 32) {
            float v = xr[k] / norm;
            xo[k] = v;
            oh[k] = __float2half_rn(v);
        }
    } else if (b < nbN + nbT) {
        // ---- transpose cb [K,N] -> [N,K] + fp16 split ----
        int bb = b - nbN;
        int n0 = (bb & 255) * 32;          // NC/32 = 256 tiles in n
        int k0 = (bb >> 8) * 32;
        int tx = tid & 31, ty = tid >> 5;  // 32 x 8
        #pragma unroll
        for (int j = 0; j < 4; j++)
            t[ty + 8 * j][tx] = cb[(size_t)(k0 + ty + 8 * j) * NC + n0 + tx];
        __syncthreads();
        #pragma unroll
        for (int j = 0; j < 4; j++) {
            int n = n0 + ty + 8 * j;
            int k = k0 + tx;
            float v = t[tx][ty + 8 * j];
            g_bT[(size_t)n * DIM + k] = v;
            g_b_h[(size_t)n * DIM + k] = __float2half_rn(v);
        }
    } else {
        // ---- d2: codebook column norms ----
        int c = (b - nbN - nbT) * 256 + tid;
        if (c >= NC) return;
        float s = 0.f;
        #pragma unroll 4
        for (int k = 0; k < DIM; k++) { float v = cb[(size_t)k * NC + c]; s = fmaf(v, v, s); }
        g_d2[c] = s;
    }
}

// ---------------------------------------------------------------------------
// single-pass fp16 mma.sync GEMM 128x128, warp tile 64x32, 3-stage pipeline,
// 2 CTAs/SM. epilogue stores approx dist = d2 - 2*d3 as fp16 (streaming).
__global__ __launch_bounds__(256, 2)
void gemm_mma_kernel(int mtiles) {
    extern __shared__ char smem[];
    __shared__ float d2s[BN];

    const uint32_t sb = smem_u32(smem);
    const int tid  = threadIdx.x;
    const int wid  = tid >> 5;
    const int lane = tid & 31;

    int bid = blockIdx.x;
    int mt = bid % mtiles;
    int nt = bid / mtiles;
    const int rowBase = mt * BM;
    const int colBase = nt * BN;

    if (tid < BN) d2s[tid] = g_d2[colBase + tid];
    __syncthreads();

    const __half* Ah = g_a_h + (size_t)rowBase * DIM;
    const __half* Bh = g_b_h + (size_t)colBase * DIM;

    auto load_chunk = [&](int c, int st) {
        uint32_t base = sb + st * STAGE_BYTES;
        int kb = c * BK;
        #pragma unroll
        for (int j = 0; j < 4; j++) {              // A: 128 rows x 8 c16
            int i = tid + j * 256;
            int row = i >> 3, c16 = i & 7;
            uint32_t off = SWZ(row * 128 + c16 * 16);
            cp16(base + ST_A + off, Ah + (size_t)row * DIM + kb + c16 * 8);
        }
        #pragma unroll
        for (int j = 0; j < 4; j++) {              // B: 128 rows x 8 c16
            int i = tid + j * 256;
            int row = i >> 3, c16 = i & 7;
            uint32_t off = SWZ(row * 128 + c16 * 16);
            cp16(base + ST_B + off, Bh + (size_t)row * DIM + kb + c16 * 8);
        }
        CP_COMMIT();
    };

    // warp tiling: 2 (M) x 4 (N); warp tile 64 x 32
    const int wm = (wid >> 2) * 64;
    const int wn = (wid & 3) * 32;

    float acc[4][4][4];
    #pragma unroll
    for (int i = 0; i < 4; i++)
        #pragma unroll
        for (int j = 0; j < 4; j++)
            #pragma unroll
            for (int k = 0; k < 4; k++) acc[i][j][k] = 0.f;

    const int lm = lane >> 3;
    const int lr = lane & 7;
    const int a_row  = wm + ((lm & 1) << 3) + lr;
    const int a_koff = (lm >> 1) << 4;
    const int b_row  = wn + ((lm >> 1) << 3) + lr;
    const int b_koff = (lm & 1) << 4;

    load_chunk(0, 0);
    load_chunk(1, 1);

    for (int c = 0; c < NCH; c++) {
        if (c + 1 < NCH) {
            asm volatile("cp.async.wait_group 1;" ::: "memory");
        } else {
            asm volatile("cp.async.wait_group 0;" ::: "memory");
        }
        __syncthreads();
        if (c + 2 < NCH) load_chunk(c + 2, (c + 2) % NSTAGE);

        uint32_t base = sb + (c % NSTAGE) * STAGE_BYTES;
        #pragma unroll
        for (int ks = 0; ks < 4; ks++) {
            uint32_t ah[4][4], bh[4][2];
            #pragma unroll
            for (int ma = 0; ma < 4; ma++) {
                uint32_t ra = SWZ((a_row + ma * 16) * 128 + ks * 32 + a_koff);
                ldsm4(ah[ma][0], ah[ma][1], ah[ma][2], ah[ma][3], base + ST_A + ra);
            }
            #pragma unroll
            for (int nb = 0; nb < 2; nb++) {
                uint32_t rb = SWZ((b_row + nb * 16) * 128 + ks * 32 + b_koff);
                ldsm4(bh[2 * nb][0], bh[2 * nb][1], bh[2 * nb + 1][0], bh[2 * nb + 1][1],
                      base + ST_B + rb);
            }
            #pragma unroll
            for (int ma = 0; ma < 4; ma++)
                #pragma unroll
                for (int na = 0; na < 4; na++)
                    mma_f16(acc[ma][na], ah[ma][0], ah[ma][1], ah[ma][2], ah[ma][3],
                            bh[na][0], bh[na][1]);
        }
    }

    // ---- epilogue: store approx distances as fp16 (streaming) ----
    const int erow = lane >> 2;
    const int ecol = 2 * (lane & 3);
    #pragma unroll
    for (int ma = 0; ma < 4; ma++) {
        #pragma unroll
        for (int h = 0; h < 2; h++) {
            int row = rowBase + wm + ma * 16 + h * 8 + erow;
            #pragma unroll
            for (int na = 0; na < 4; na++) {
                int cl = wn + na * 8 + ecol;
                float dx = d2s[cl]     - 2.0f * acc[ma][na][2 * h];
                float dy = d2s[cl + 1] - 2.0f * acc[ma][na][2 * h + 1];
                __half2 hv = __floats2half2_rn(dx, dy);
                __stcs((uint32_t*)(g_dist + (size_t)row * NC + colBase + cl),
                       *(uint32_t*)&hv);
            }
        }
    }
}

// ---------------------------------------------------------------------------
// per-row: approx min, candidates within EPS, exact fp32 refine (warp/candidate)
// writes g_idx AND (optionally) the float inds output directly.
__global__ __launch_bounds__(256, 4)
void select_kernel(float* __restrict__ out_inds) {
    __shared__ unsigned long long wmin[8];
    __shared__ unsigned long long rowmin_s;
    __shared__ unsigned long long sbest;
    __shared__ int cands[MAXCAND];
    __shared__ int ncand;

    const int row  = blockIdx.x;
    const int tid  = threadIdx.x;
    const int wid  = tid >> 5;
    const int lane = tid & 31;

    const uint4* dr4 = (const uint4*)(g_dist + (size_t)row * NC);

    float v[32];
    unsigned long long key = ~0ull;
    #pragma unroll
    for (int j = 0; j < 4; j++) {
        uint4 q = dr4[tid + 256 * j];
        int cbase = (tid + 256 * j) * 8;
        uint32_t w[4] = {q.x, q.y, q.z, q.w};
        #pragma unroll
        for (int p = 0; p < 4; p++) {
            __half2 h2 = *(__half2*)&w[p];
            float2 f = __half22float2(h2);
            v[j * 8 + 2 * p]     = f.x;
            v[j * 8 + 2 * p + 1] = f.y;
            unsigned long long pk0 =
                ((unsigned long long)fkey(f.x) << 32) | (unsigned int)(cbase + 2 * p);
            unsigned long long pk1 =
                ((unsigned long long)fkey(f.y) << 32) | (unsigned int)(cbase + 2 * p + 1);
            key = (pk0 < key) ? pk0 : key;
            key = (pk1 < key) ? pk1 : key;
        }
    }
    #pragma unroll
    for (int o = 16; o; o >>= 1) {
        unsigned long long other = __shfl_xor_sync(0xFFFFFFFFu, key, o);
        key = (other < key) ? other : key;
    }
    if (lane == 0) wmin[wid] = key;
    if (tid == 0) { ncand = 0; sbest = ~0ull; }
    __syncthreads();
    if (tid == 0) {
        unsigned long long k = wmin[0];
        #pragma unroll
        for (int w = 1; w < 8; w++) k = (wmin[w] < k) ? wmin[w] : k;
        rowmin_s = k;
    }
    __syncthreads();

    unsigned long long rk = rowmin_s;
    unsigned int mku = (unsigned int)(rk >> 32);
    float m = (mku & 0x80000000u) ? __uint_as_float(mku & 0x7FFFFFFFu)
                                  : __uint_as_float(~mku);
    float thr = m + EPS;

    #pragma unroll
    for (int j = 0; j < 32; j++) {
        if (v[j] <= thr) {
            int c = ((tid + 256 * (j >> 3)) * 8) + (j & 7);
            int p = atomicAdd(&ncand, 1);
            if (p < MAXCAND) cands[p] = c;
        }
    }
    __syncthreads();

    int nc = ncand; if (nc > MAXCAND) nc = MAXCAND;
    if (nc <= 1) {
        if (tid == 0) {
            int idx = (int)(rk & 0xFFFFFFFFull);
            g_idx[row] = idx;
            if (out_inds) out_inds[row] = (float)idx;
        }
        return;
    }

    // exact fp32 refine: one warp per candidate, round-robin
    const float* xr = g_xf + (size_t)row * DIM;
    for (int ci = wid; ci < nc; ci += 8) {
        int c = cands[ci];
        const float* bc = g_bT + (size_t)c * DIM;
        float p = 0.f;
        #pragma unroll
        for (int e = 0; e < DIM / 32; e++) {
            int k = lane + 32 * e;
            p = fmaf(xr[k], bc[k], p);
        }
        #pragma unroll
        for (int o = 16; o; o >>= 1) p += __shfl_xor_sync(0xFFFFFFFFu, p, o);
        if (lane == 0) {
            float dist = g_d2[c] - 2.0f * p;
            unsigned long long pk =
                ((unsigned long long)fkey(dist) << 32) | (unsigned int)c;
            atomicMin(&sbest, pk);
        }
    }
    __syncthreads();
    if (tid == 0) {
        int idx = (int)(sbest & 0xFFFFFFFFull);
        g_idx[row] = idx;
        if (out_inds) out_inds[row] = (float)idx;
    }
}

// ---------------------------------------------------------------------------
// tiled transpose-gather: block = 32 rows x 32 dims, both sides coalesced.
// quantized[d, r] = g_bT[ind[r]][d]
__global__ void gather_kernel(float* __restrict__ out, int n_rows, long long offset) {
    __shared__ float t[32][33];
    __shared__ int sidx[32];

    const int tid = threadIdx.x;
    const int tx = tid & 31, ty = tid >> 5;     // 32 x 8
    const int r0 = blockIdx.x * 32;
    const int d0 = blockIdx.y * 32;

    if (tid < 32) {
        int r = r0 + tid;
        sidx[tid] = (r < n_rows) ? g_idx[r] : 0;
    }
    __syncthreads();

    #pragma unroll
    for (int j = 0; j < 4; j++) {
        int rl = ty + 8 * j;                     // local row
        t[rl][tx] = g_bT[(size_t)sidx[rl] * DIM + d0 + tx];
    }
    __syncthreads();

    #pragma unroll
    for (int j = 0; j < 4; j++) {
        int d = d0 + ty + 8 * j;
        int r = r0 + tx;
        if (r < n_rows)
            out[offset + (size_t)d * n_rows + r] = t[tx][ty + 8 * j];
    }
}

// ---------------------------------------------------------------------------
extern "C" void kernel_launch(void* const* d_in, const int* in_sizes, int n_in,
                              void* d_out, int out_size) {
    const float* x  = (const float*)d_in[0];
    const float* cb = (const float*)d_in[1];
    float* out = (float*)d_out;

    int n_rows = in_sizes[0] / DIM;
    if (n_rows > MAX_ROWS) n_rows = MAX_ROWS;

    static int smem_set = 0;
    if (!smem_set) {
        cudaFuncSetAttribute(gemm_mma_kernel,
                             cudaFuncAttributeMaxDynamicSharedMemorySize, SMEM_DYN);
        smem_set = 1;
    }

    // phase 0: fused prep (normalize | transpose | d2 run concurrently)
    int nbN = (n_rows * 32 + 255) / 256;
    int nbT = (NC / 32) * (DIM / 32);
    int nbD = (NC + 255) / 256;
    prep_kernel<<<nbN + nbT + nbD, 256>>>(x, cb, n_rows, nbN, nbT);

    // phase 1: single-pass fp16 GEMM -> approx dist matrix (fp16)
    int mtiles = (n_rows + BM - 1) / BM;
    gemm_mma_kernel<<<mtiles * TILES_N, 256, SMEM_DYN>>>(mtiles);

    // phase 2+3: selection (+ inds output fused) then tiled gather
    long long full = (long long)n_rows + (long long)n_rows * DIM;
    dim3 gg((n_rows + 31) / 32, DIM / 32);
    if ((long long)out_size >= full) {
        select_kernel<<<n_rows, 256>>>(out);
        gather_kernel<<<gg, 256>>>(out, n_rows, (long long)n_rows);
    } else if ((long long)out_size == (long long)n_rows * DIM) {
        select_kernel<<<n_rows, 256>>>(nullptr);
        gather_kernel<<<gg, 256>>>(out, n_rows, 0);
    } else {
        select_kernel<<<n_rows, 256>>>(out);
    }
}